// round 2
// baseline (speedup 1.0000x reference)
#include <cuda_runtime.h>
#include <math.h>

#define NSAMP 64000
#define TILE  32
#define NTHR  256
#define SPB   8000   // samples per batch element (N/B)

// Precombined (expert-mixed) weights, TRANSPOSED to [b][i][o] so phase-2 can
// do one uniform LDG.128 per 4 output dims.
__device__ __align__(16) float g_Wt0[8 * 192 * 192];
__device__ __align__(16) float g_bc0[8 * 192];
__device__ __align__(16) float g_Wt1[8 * 128 * 256];
__device__ __align__(16) float g_Wt2[8 * 64 * 128];

__global__ void prep_weights_kernel(
    const float* __restrict__ coef,
    const float* __restrict__ w0, const float* __restrict__ b0,
    const float* __restrict__ ws0, const float* __restrict__ bs0,
    const float* __restrict__ w1, const float* __restrict__ ws1,
    const float* __restrict__ w2, const float* __restrict__ ws2)
{
    int idx = blockIdx.x * blockDim.x + threadIdx.x;
    const int S0 = 8 * 192 * 192;
    const int S1 = 8 * 192;
    const int S2 = 8 * 128 * 256;
    const int S3 = 8 * 64 * 128;
    if (idx < S0) {
        int b = idx / 36864, r = idx % 36864;
        int i = r / 192, o = r % 192;
        float v = ws0[o * 192 + i];
        #pragma unroll
        for (int e = 0; e < 8; e++)
            v = fmaf(coef[b * 8 + e], w0[e * 36864 + o * 192 + i], v);
        g_Wt0[b * 36864 + i * 192 + o] = v;
        return;
    }
    idx -= S0;
    if (idx < S1) {
        int b = idx / 192, o = idx % 192;
        float v = bs0[o];
        #pragma unroll
        for (int e = 0; e < 8; e++)
            v = fmaf(coef[b * 8 + e], b0[e * 192 + o], v);
        g_bc0[b * 192 + o] = v;
        return;
    }
    idx -= S1;
    if (idx < S2) {
        int b = idx / 32768, r = idx % 32768;
        int i = r / 256, o = r % 256;
        float v = ws1[o * 128 + i];
        #pragma unroll
        for (int e = 0; e < 8; e++)
            v = fmaf(coef[b * 8 + e], w1[e * 32768 + o * 128 + i], v);
        g_Wt1[b * 32768 + i * 256 + o] = v;
        return;
    }
    idx -= S2;
    if (idx < S3) {
        int b = idx / 8192, r = idx % 8192;
        int i = r / 128, o = r % 128;
        float v = ws2[o * 64 + i];
        #pragma unroll
        for (int e = 0; e < 8; e++)
            v = fmaf(coef[b * 8 + e], w2[e * 8192 + o * 64 + i], v);
        g_Wt2[b * 8192 + i * 128 + o] = v;
    }
}

// ---- dense small matmuls for the Wigner chain ----
__device__ __forceinline__ void mm3(const float* P, const float* Q, float* R) {
    #pragma unroll
    for (int i = 0; i < 3; i++)
        #pragma unroll
        for (int j = 0; j < 3; j++) {
            float acc = 0.f;
            #pragma unroll
            for (int k = 0; k < 3; k++) acc = fmaf(P[i * 3 + k], Q[k * 3 + j], acc);
            R[i * 3 + j] = acc;
        }
}
__device__ __forceinline__ void mm5(const float* P, const float* Q, float* R) {
    #pragma unroll
    for (int i = 0; i < 5; i++)
        #pragma unroll
        for (int j = 0; j < 5; j++) {
            float acc = 0.f;
            #pragma unroll
            for (int k = 0; k < 5; k++) acc = fmaf(P[i * 5 + k], Q[k * 5 + j], acc);
            R[i * 5 + j] = acc;
        }
}

// D_l = X_l(a1) @ J_l @ X_l(a2) @ J_l @ X_l(a3), l = 1 (3x3) and 2 (5x5).
// X1(a) = [[c,0,s],[0,1,0],[-s,0,c]]
// X2(a) = [[c2,0,0,0,s2],[0,c,0,s,0],[0,0,1,0,0],[0,-s,0,c,0],[-s2,0,0,0,c2]]
__device__ void build_D(float a1, float a2, float a3,
                        const float* __restrict__ J1g,
                        const float* __restrict__ J2g,
                        float* __restrict__ D1, float* __restrict__ D2)
{
    float J1[9], J2[25];
    #pragma unroll
    for (int i = 0; i < 9; i++) J1[i] = J1g[i];
    #pragma unroll
    for (int i = 0; i < 25; i++) J2[i] = J2g[i];

    float X[3][9], Y[3][25];
    float aa[3] = {a1, a2, a3};
    #pragma unroll
    for (int t = 0; t < 3; t++) {
        double s1d, c1d, s2d, c2d;
        sincos((double)aa[t], &s1d, &c1d);
        sincos(2.0 * (double)aa[t], &s2d, &c2d);
        float c1 = (float)c1d, s1 = (float)s1d, c2 = (float)c2d, s2 = (float)s2d;
        float* Xp = X[t];
        Xp[0] = c1;  Xp[1] = 0.f; Xp[2] = s1;
        Xp[3] = 0.f; Xp[4] = 1.f; Xp[5] = 0.f;
        Xp[6] = -s1; Xp[7] = 0.f; Xp[8] = c1;
        float* Yp = Y[t];
        #pragma unroll
        for (int q = 0; q < 25; q++) Yp[q] = 0.f;
        Yp[0]  = c2;  Yp[4]  = s2;
        Yp[6]  = c1;  Yp[8]  = s1;
        Yp[12] = 1.f;
        Yp[16] = -s1; Yp[18] = c1;
        Yp[20] = -s2; Yp[24] = c2;
    }
    float T1[9], T2[9];
    mm3(X[0], J1, T1);
    mm3(T1, X[1], T2);
    mm3(T2, J1, T1);
    mm3(T1, X[2], D1);
    float U1[25], U2[25];
    mm5(Y[0], J2, U1);
    mm5(U1, Y[1], U2);
    mm5(U2, J2, U1);
    mm5(U1, Y[2], D2);
}

// SMEM layout (floats):
//   A   [576*33]   gathered inputs [gdim][sample], stride 33 (conflict-free)
//   Bb  [18464]    raw x [s][577] in phase 1 -> pre-rotation output [dim][32] in phase 2/3
//   D1f [32*9], D2f [32*25], D1b [32*9], D2b [32*25]
#define SM_A    0
#define SM_BB   (576 * 33)
#define SM_D1F  (SM_BB + 18464)
#define SM_D2F  (SM_D1F + 288)
#define SM_D1B  (SM_D2F + 800)
#define SM_D2B  (SM_D1B + 288)
#define SM_TOT  (SM_D2B + 800)

__global__ __launch_bounds__(NTHR, 1)
void so2_main_kernel(const float* __restrict__ x,
                     const float* __restrict__ alpha,
                     const float* __restrict__ beta,
                     const float* __restrict__ gamma_,
                     const float* __restrict__ Jd1,
                     const float* __restrict__ Jd2,
                     float* __restrict__ out)
{
    extern __shared__ float sm[];
    float* A   = sm + SM_A;
    float* Bb  = sm + SM_BB;
    float* D1f = sm + SM_D1F;
    float* D2f = sm + SM_D2F;
    float* D1b = sm + SM_D1B;
    float* D2b = sm + SM_D2B;

    const int tid  = threadIdx.x;
    const int w    = tid >> 5;
    const int lane = tid & 31;
    const int n0   = blockIdx.x * TILE;
    const int b    = n0 / SPB;

    // ---- Phase 1a/1b: threads 0..63 build Wigner matrices; 64..255 stage x ----
    if (tid < 64) {
        int s = tid & 31;
        int n = n0 + s;
        float al = alpha[n], be = beta[n], ga = gamma_[n];
        if (tid < 32)
            build_D(al, be, ga, Jd1, Jd2, D1f + s * 9, D2f + s * 25);
        else
            build_D(-ga, -be, -al, Jd1, Jd2, D1b + s * 9, D2b + s * 25);
    } else {
        const float* xg = x + (size_t)n0 * 576;
        for (int idx = tid - 64; idx < TILE * 576; idx += NTHR - 64) {
            int s = idx / 576, d = idx % 576;
            Bb[s * 577 + d] = xg[idx];
        }
    }
    __syncthreads();

    // ---- Phase 1c: rotate (fwd Wigner) + gather into A[gdim][sample] ----
    // gdim: [0..191] m0 in; [192..319] m1 j=0; [320..447] m1 j=1; [448..511] m2 j=0; [512..575] m2 j=1
    {
        float d1[9], d2[25];
        #pragma unroll
        for (int j = 0; j < 9; j++)  d1[j] = D1f[lane * 9 + j];
        #pragma unroll
        for (int j = 0; j < 25; j++) d2[j] = D2f[lane * 25 + j];
        const float* br = Bb + lane * 577;
        #pragma unroll
        for (int k = 0; k < 8; k++) {
            int c = w + 8 * k;
            // l=0
            A[c * 33 + lane] = br[c];
            // l=1: r = D1 @ v ; comp0->m1 j0, comp1->m0, comp2->m1 j1
            float v0 = br[64 + 3 * c], v1 = br[64 + 3 * c + 1], v2 = br[64 + 3 * c + 2];
            A[(192 + c) * 33 + lane] = fmaf(d1[0], v0, fmaf(d1[1], v1, d1[2] * v2));
            A[(64  + c) * 33 + lane] = fmaf(d1[3], v0, fmaf(d1[4], v1, d1[5] * v2));
            A[(320 + c) * 33 + lane] = fmaf(d1[6], v0, fmaf(d1[7], v1, d1[8] * v2));
            // l=2: rr = D2 @ u ; comps 0,1,2,3,4 -> m2j0, m1j0, m0, m1j1, m2j1
            float u0 = br[256 + 5 * c],     u1 = br[256 + 5 * c + 1], u2 = br[256 + 5 * c + 2];
            float u3 = br[256 + 5 * c + 3], u4 = br[256 + 5 * c + 4];
            float rr[5];
            #pragma unroll
            for (int i = 0; i < 5; i++)
                rr[i] = fmaf(d2[i*5+0], u0, fmaf(d2[i*5+1], u1, fmaf(d2[i*5+2], u2,
                        fmaf(d2[i*5+3], u3, d2[i*5+4] * u4))));
            A[(448 + c) * 33 + lane] = rr[0];
            A[(256 + c) * 33 + lane] = rr[1];
            A[(128 + c) * 33 + lane] = rr[2];
            A[(384 + c) * 33 + lane] = rr[3];
            A[(512 + c) * 33 + lane] = rr[4];
        }
    }
    __syncthreads();

    // ---- Phase 2: batched GEMVs, lanes = samples, warp-uniform LDG.128 weights ----
    // 96 task-groups of 4 outputs: [0..47] m0, [48..79] m1, [80..95] m2
    {
        const float* Ax = A + lane;
        for (int t = 0; t < 12; t++) {
            int g = w + 8 * t;
            if (g < 48) {
                int o0 = g * 4;
                const float* wp = g_Wt0 + b * 36864 + o0;
                const float* bp = g_bc0 + b * 192 + o0;
                float a0 = bp[0], a1 = bp[1], a2 = bp[2], a3 = bp[3];
                #pragma unroll 4
                for (int i = 0; i < 192; i++) {
                    float xv = Ax[i * 33];
                    float4 wv = *reinterpret_cast<const float4*>(wp + i * 192);
                    a0 = fmaf(wv.x, xv, a0);
                    a1 = fmaf(wv.y, xv, a1);
                    a2 = fmaf(wv.z, xv, a2);
                    a3 = fmaf(wv.w, xv, a3);
                }
                float acc[4] = {a0, a1, a2, a3};
                #pragma unroll
                for (int u = 0; u < 4; u++) {
                    int o = o0 + u;
                    int dim = (o < 64) ? o : (o < 128) ? (64 + 3 * (o - 64) + 1)
                                                       : (256 + 5 * (o - 128) + 2);
                    Bb[dim * 32 + lane] = acc[u];
                }
            } else if (g < 80) {
                int k0 = (g - 48) * 4;
                const float* wp  = g_Wt1 + b * 32768 + k0;
                const float* a0p = Ax + 192 * 33;
                const float* a1p = Ax + 320 * 33;
                float yr0[4] = {0,0,0,0}, yi0[4] = {0,0,0,0};
                float yr1[4] = {0,0,0,0}, yi1[4] = {0,0,0,0};
                #pragma unroll 2
                for (int i = 0; i < 128; i++) {
                    float x0 = a0p[i * 33];
                    float x1 = a1p[i * 33];
                    float4 wr4 = *reinterpret_cast<const float4*>(wp + i * 256);
                    float4 wi4 = *reinterpret_cast<const float4*>(wp + i * 256 + 128);
                    float wr[4] = {wr4.x, wr4.y, wr4.z, wr4.w};
                    float wi[4] = {wi4.x, wi4.y, wi4.z, wi4.w};
                    #pragma unroll
                    for (int u = 0; u < 4; u++) {
                        yr0[u] = fmaf(wr[u], x0, yr0[u]);
                        yr1[u] = fmaf(wr[u], x1, yr1[u]);
                        yi0[u] = fmaf(wi[u], x0, yi0[u]);
                        yi1[u] = fmaf(wi[u], x1, yi1[u]);
                    }
                }
                #pragma unroll
                for (int u = 0; u < 4; u++) {
                    int k = k0 + u;
                    float om = yr0[u] - yi1[u];
                    float op = yr1[u] + yi0[u];
                    int dm = (k < 64) ? (64 + 3 * k)     : (256 + 5 * (k - 64) + 1);
                    int dp = (k < 64) ? (64 + 3 * k + 2) : (256 + 5 * (k - 64) + 3);
                    Bb[dm * 32 + lane] = om;
                    Bb[dp * 32 + lane] = op;
                }
            } else {
                int k0 = (g - 80) * 4;
                const float* wp  = g_Wt2 + b * 8192 + k0;
                const float* a0p = Ax + 448 * 33;
                const float* a1p = Ax + 512 * 33;
                float yr0[4] = {0,0,0,0}, yi0[4] = {0,0,0,0};
                float yr1[4] = {0,0,0,0}, yi1[4] = {0,0,0,0};
                #pragma unroll 2
                for (int i = 0; i < 64; i++) {
                    float x0 = a0p[i * 33];
                    float x1 = a1p[i * 33];
                    float4 wr4 = *reinterpret_cast<const float4*>(wp + i * 128);
                    float4 wi4 = *reinterpret_cast<const float4*>(wp + i * 128 + 64);
                    float wr[4] = {wr4.x, wr4.y, wr4.z, wr4.w};
                    float wi[4] = {wi4.x, wi4.y, wi4.z, wi4.w};
                    #pragma unroll
                    for (int u = 0; u < 4; u++) {
                        yr0[u] = fmaf(wr[u], x0, yr0[u]);
                        yr1[u] = fmaf(wr[u], x1, yr1[u]);
                        yi0[u] = fmaf(wi[u], x0, yi0[u]);
                        yi1[u] = fmaf(wi[u], x1, yi1[u]);
                    }
                }
                #pragma unroll
                for (int u = 0; u < 4; u++) {
                    int k = k0 + u;
                    float om = yr0[u] - yi1[u];
                    float op = yr1[u] + yi0[u];
                    Bb[(256 + 5 * k) * 32 + lane]     = om;
                    Bb[(256 + 5 * k + 4) * 32 + lane] = op;
                }
            }
        }
    }
    __syncthreads();

    // ---- Phase 3: back-rotation (inverse Wigner), write final into A[dim][s] ----
    {
        float e1[9], e2[25];
        #pragma unroll
        for (int j = 0; j < 9; j++)  e1[j] = D1b[lane * 9 + j];
        #pragma unroll
        for (int j = 0; j < 25; j++) e2[j] = D2b[lane * 25 + j];
        const float* bp = Bb + lane;
        float* Ao = A + lane;
        #pragma unroll
        for (int k = 0; k < 8; k++) {
            int c = w + 8 * k;
            Ao[c * 33] = bp[c * 32];  // l=0 block of D is identity
            float v0 = bp[(64 + 3 * c) * 32], v1 = bp[(64 + 3 * c + 1) * 32], v2 = bp[(64 + 3 * c + 2) * 32];
            Ao[(64 + 3 * c) * 33]     = fmaf(e1[0], v0, fmaf(e1[1], v1, e1[2] * v2));
            Ao[(64 + 3 * c + 1) * 33] = fmaf(e1[3], v0, fmaf(e1[4], v1, e1[5] * v2));
            Ao[(64 + 3 * c + 2) * 33] = fmaf(e1[6], v0, fmaf(e1[7], v1, e1[8] * v2));
            float u0 = bp[(256 + 5 * c) * 32],     u1 = bp[(256 + 5 * c + 1) * 32];
            float u2 = bp[(256 + 5 * c + 2) * 32], u3 = bp[(256 + 5 * c + 3) * 32];
            float u4 = bp[(256 + 5 * c + 4) * 32];
            #pragma unroll
            for (int i = 0; i < 5; i++)
                Ao[(256 + 5 * c + i) * 33] =
                    fmaf(e2[i*5+0], u0, fmaf(e2[i*5+1], u1, fmaf(e2[i*5+2], u2,
                    fmaf(e2[i*5+3], u3, e2[i*5+4] * u4))));
        }
    }
    __syncthreads();

    // ---- Store: coalesced global write ----
    {
        float* og = out + (size_t)n0 * 576;
        for (int idx = tid; idx < TILE * 576; idx += NTHR) {
            int s = idx / 576, d = idx % 576;
            og[idx] = A[d * 33 + s];
        }
    }
}

extern "C" void kernel_launch(void* const* d_in, const int* in_sizes, int n_in,
                              void* d_out, int out_size)
{
    const float* x     = (const float*)d_in[0];
    const float* alpha = (const float*)d_in[1];
    const float* beta  = (const float*)d_in[2];
    const float* gamma_= (const float*)d_in[3];
    const float* coef  = (const float*)d_in[4];
    const float* Jd1   = (const float*)d_in[5];
    const float* Jd2   = (const float*)d_in[6];
    const float* w0    = (const float*)d_in[7];
    const float* b0    = (const float*)d_in[8];
    const float* ws0   = (const float*)d_in[9];
    const float* bs0   = (const float*)d_in[10];
    const float* w1    = (const float*)d_in[11];
    const float* ws1   = (const float*)d_in[12];
    const float* w2    = (const float*)d_in[13];
    const float* ws2   = (const float*)d_in[14];
    float* out = (float*)d_out;

    const int totalW = 8 * 192 * 192 + 8 * 192 + 8 * 128 * 256 + 8 * 64 * 128;
    prep_weights_kernel<<<(totalW + 255) / 256, 256>>>(coef, w0, b0, ws0, bs0,
                                                       w1, ws1, w2, ws2);

    const int smem_bytes = SM_TOT * sizeof(float);
    cudaFuncSetAttribute(so2_main_kernel,
                         cudaFuncAttributeMaxDynamicSharedMemorySize, smem_bytes);
    so2_main_kernel<<<NSAMP / TILE, NTHR, smem_bytes>>>(x, alpha, beta, gamma_,
                                                        Jd1, Jd2, out);
}

// round 3
// speedup vs baseline: 1.6486x; 1.6486x over previous
#include <cuda_runtime.h>
#include <math.h>

#define NSAMP 64000
#define TILE  32
#define NTHR  512
#define NWARP 16
#define SPB   8000   // samples per batch element (N/B)

// Precombined (expert-mixed) weights, TRANSPOSED to [b][i][o] so phase-2 can
// do one uniform LDG.128 per 4 output dims.
__device__ __align__(16) float g_Wt0[8 * 192 * 192];
__device__ __align__(16) float g_bc0[8 * 192];
__device__ __align__(16) float g_Wt1[8 * 128 * 256];
__device__ __align__(16) float g_Wt2[8 * 64 * 128];

__global__ void prep_weights_kernel(
    const float* __restrict__ coef,
    const float* __restrict__ w0, const float* __restrict__ b0,
    const float* __restrict__ ws0, const float* __restrict__ bs0,
    const float* __restrict__ w1, const float* __restrict__ ws1,
    const float* __restrict__ w2, const float* __restrict__ ws2)
{
    int idx = blockIdx.x * blockDim.x + threadIdx.x;
    const int S0 = 8 * 192 * 192;
    const int S1 = 8 * 192;
    const int S2 = 8 * 128 * 256;
    const int S3 = 8 * 64 * 128;
    if (idx < S0) {
        int b = idx / 36864, r = idx % 36864;
        int i = r / 192, o = r % 192;
        float v = ws0[o * 192 + i];
        #pragma unroll
        for (int e = 0; e < 8; e++)
            v = fmaf(coef[b * 8 + e], w0[e * 36864 + o * 192 + i], v);
        g_Wt0[b * 36864 + i * 192 + o] = v;
        return;
    }
    idx -= S0;
    if (idx < S1) {
        int b = idx / 192, o = idx % 192;
        float v = bs0[o];
        #pragma unroll
        for (int e = 0; e < 8; e++)
            v = fmaf(coef[b * 8 + e], b0[e * 192 + o], v);
        g_bc0[b * 192 + o] = v;
        return;
    }
    idx -= S1;
    if (idx < S2) {
        int b = idx / 32768, r = idx % 32768;
        int i = r / 256, o = r % 256;
        float v = ws1[o * 128 + i];
        #pragma unroll
        for (int e = 0; e < 8; e++)
            v = fmaf(coef[b * 8 + e], w1[e * 32768 + o * 128 + i], v);
        g_Wt1[b * 32768 + i * 256 + o] = v;
        return;
    }
    idx -= S2;
    if (idx < S3) {
        int b = idx / 8192, r = idx % 8192;
        int i = r / 128, o = r % 128;
        float v = ws2[o * 64 + i];
        #pragma unroll
        for (int e = 0; e < 8; e++)
            v = fmaf(coef[b * 8 + e], w2[e * 8192 + o * 64 + i], v);
        g_Wt2[b * 8192 + i * 128 + o] = v;
    }
}

// ---- dense small matmuls for the Wigner chain ----
__device__ __forceinline__ void mm3(const float* P, const float* Q, float* R) {
    #pragma unroll
    for (int i = 0; i < 3; i++)
        #pragma unroll
        for (int j = 0; j < 3; j++) {
            float acc = 0.f;
            #pragma unroll
            for (int k = 0; k < 3; k++) acc = fmaf(P[i * 3 + k], Q[k * 3 + j], acc);
            R[i * 3 + j] = acc;
        }
}
__device__ __forceinline__ void mm5(const float* P, const float* Q, float* R) {
    #pragma unroll
    for (int i = 0; i < 5; i++)
        #pragma unroll
        for (int j = 0; j < 5; j++) {
            float acc = 0.f;
            #pragma unroll
            for (int k = 0; k < 5; k++) acc = fmaf(P[i * 5 + k], Q[k * 5 + j], acc);
            R[i * 5 + j] = acc;
        }
}

// D_l = X_l(a1) @ J_l @ X_l(a2) @ J_l @ X_l(a3), l = 1 (3x3) and 2 (5x5).
__device__ void build_D(float a1, float a2, float a3,
                        const float* __restrict__ J1g,
                        const float* __restrict__ J2g,
                        float* __restrict__ D1, float* __restrict__ D2)
{
    float J1[9], J2[25];
    #pragma unroll
    for (int i = 0; i < 9; i++) J1[i] = J1g[i];
    #pragma unroll
    for (int i = 0; i < 25; i++) J2[i] = J2g[i];

    float X[3][9], Y[3][25];
    float aa[3] = {a1, a2, a3};
    #pragma unroll
    for (int t = 0; t < 3; t++) {
        float c1, s1, c2, s2;
        sincosf(aa[t], &s1, &c1);
        sincosf(2.0f * aa[t], &s2, &c2);
        float* Xp = X[t];
        Xp[0] = c1;  Xp[1] = 0.f; Xp[2] = s1;
        Xp[3] = 0.f; Xp[4] = 1.f; Xp[5] = 0.f;
        Xp[6] = -s1; Xp[7] = 0.f; Xp[8] = c1;
        float* Yp = Y[t];
        #pragma unroll
        for (int q = 0; q < 25; q++) Yp[q] = 0.f;
        Yp[0]  = c2;  Yp[4]  = s2;
        Yp[6]  = c1;  Yp[8]  = s1;
        Yp[12] = 1.f;
        Yp[16] = -s1; Yp[18] = c1;
        Yp[20] = -s2; Yp[24] = c2;
    }
    float T1[9], T2[9];
    mm3(X[0], J1, T1);
    mm3(T1, X[1], T2);
    mm3(T2, J1, T1);
    mm3(T1, X[2], D1);
    float U1[25], U2[25];
    mm5(Y[0], J2, U1);
    mm5(U1, Y[1], U2);
    mm5(U2, J2, U1);
    mm5(U1, Y[2], D2);
}

// SMEM layout (floats):
//   A   [576*33]   gathered inputs [gdim][sample], stride 33 (conflict-free)
//   Bb  [18464]    raw x [s][577] in phase 1 -> pre-rotation output [dim][32] in phase 2/3
//   D1f [32*9], D2f [32*25], D1b [32*9], D2b [32*25]
#define SM_A    0
#define SM_BB   (576 * 33)
#define SM_D1F  (SM_BB + 18464)
#define SM_D2F  (SM_D1F + 288)
#define SM_D1B  (SM_D2F + 800)
#define SM_D2B  (SM_D1B + 288)
#define SM_TOT  (SM_D2B + 800)

__global__ __launch_bounds__(NTHR, 1)
void so2_main_kernel(const float* __restrict__ x,
                     const float* __restrict__ alpha,
                     const float* __restrict__ beta,
                     const float* __restrict__ gamma_,
                     const float* __restrict__ Jd1,
                     const float* __restrict__ Jd2,
                     float* __restrict__ out)
{
    extern __shared__ float sm[];
    float* A   = sm + SM_A;
    float* Bb  = sm + SM_BB;
    float* D1f = sm + SM_D1F;
    float* D2f = sm + SM_D2F;
    float* D1b = sm + SM_D1B;
    float* D2b = sm + SM_D2B;

    const int tid  = threadIdx.x;
    const int w    = tid >> 5;
    const int lane = tid & 31;
    const int n0   = blockIdx.x * TILE;
    const int b    = n0 / SPB;

    // ---- Phase 1a/1b: warps 0-1 build Wigner matrices; warps 2-15 stage x ----
    if (tid < 64) {
        int s = tid & 31;
        int n = n0 + s;
        float al = alpha[n], be = beta[n], ga = gamma_[n];
        if (tid < 32)
            build_D(al, be, ga, Jd1, Jd2, D1f + s * 9, D2f + s * 25);
        else
            build_D(-ga, -be, -al, Jd1, Jd2, D1b + s * 9, D2b + s * 25);
    } else {
        const float* xg = x + (size_t)n0 * 576;
        for (int idx = tid - 64; idx < TILE * 576; idx += NTHR - 64) {
            int s = idx / 576, d = idx % 576;
            Bb[s * 577 + d] = xg[idx];
        }
    }
    __syncthreads();

    // ---- Phase 1c: rotate (fwd Wigner) + gather into A[gdim][sample] ----
    // gdim: [0..191] m0; [192..319] m1 j=0; [320..447] m1 j=1; [448..511] m2 j=0; [512..575] m2 j=1
    {
        float d1[9], d2[25];
        #pragma unroll
        for (int j = 0; j < 9; j++)  d1[j] = D1f[lane * 9 + j];
        #pragma unroll
        for (int j = 0; j < 25; j++) d2[j] = D2f[lane * 25 + j];
        const float* br = Bb + lane * 577;
        #pragma unroll
        for (int k = 0; k < 4; k++) {
            int c = w + NWARP * k;
            A[c * 33 + lane] = br[c];
            float v0 = br[64 + 3 * c], v1 = br[64 + 3 * c + 1], v2 = br[64 + 3 * c + 2];
            A[(192 + c) * 33 + lane] = fmaf(d1[0], v0, fmaf(d1[1], v1, d1[2] * v2));
            A[(64  + c) * 33 + lane] = fmaf(d1[3], v0, fmaf(d1[4], v1, d1[5] * v2));
            A[(320 + c) * 33 + lane] = fmaf(d1[6], v0, fmaf(d1[7], v1, d1[8] * v2));
            float u0 = br[256 + 5 * c],     u1 = br[256 + 5 * c + 1], u2 = br[256 + 5 * c + 2];
            float u3 = br[256 + 5 * c + 3], u4 = br[256 + 5 * c + 4];
            float rr[5];
            #pragma unroll
            for (int i = 0; i < 5; i++)
                rr[i] = fmaf(d2[i*5+0], u0, fmaf(d2[i*5+1], u1, fmaf(d2[i*5+2], u2,
                        fmaf(d2[i*5+3], u3, d2[i*5+4] * u4))));
            A[(448 + c) * 33 + lane] = rr[0];
            A[(256 + c) * 33 + lane] = rr[1];
            A[(128 + c) * 33 + lane] = rr[2];
            A[(384 + c) * 33 + lane] = rr[3];
            A[(512 + c) * 33 + lane] = rr[4];
        }
    }
    __syncthreads();

    // ---- Phase 2: batched GEMVs, lanes = samples, warp-uniform LDG.128 weights,
    //      explicit 8-deep (m0) / 4-deep (m1,m2) load batching for MLP ----
    {
        const float* Ax = A + lane;
        #pragma unroll 1
        for (int t = 0; t < 6; t++) {
            int g = w + NWARP * t;
            if (g < 48) {
                int o0 = g * 4;
                const float* wp = g_Wt0 + b * 36864 + o0;
                const float* bp = g_bc0 + b * 192 + o0;
                float a0 = bp[0], a1 = bp[1], a2 = bp[2], a3 = bp[3];
                #pragma unroll 1
                for (int i = 0; i < 192; i += 8) {
                    float4 wv[8];
                    float  xv[8];
                    #pragma unroll
                    for (int u = 0; u < 8; u++)
                        wv[u] = *reinterpret_cast<const float4*>(wp + (i + u) * 192);
                    #pragma unroll
                    for (int u = 0; u < 8; u++)
                        xv[u] = Ax[(i + u) * 33];
                    #pragma unroll
                    for (int u = 0; u < 8; u++) {
                        a0 = fmaf(wv[u].x, xv[u], a0);
                        a1 = fmaf(wv[u].y, xv[u], a1);
                        a2 = fmaf(wv[u].z, xv[u], a2);
                        a3 = fmaf(wv[u].w, xv[u], a3);
                    }
                }
                float acc[4] = {a0, a1, a2, a3};
                #pragma unroll
                for (int u = 0; u < 4; u++) {
                    int o = o0 + u;
                    int dim = (o < 64) ? o : (o < 128) ? (64 + 3 * (o - 64) + 1)
                                                       : (256 + 5 * (o - 128) + 2);
                    Bb[dim * 32 + lane] = acc[u];
                }
            } else if (g < 80) {
                int k0 = (g - 48) * 4;
                const float* wp  = g_Wt1 + b * 32768 + k0;
                const float* a0p = Ax + 192 * 33;
                const float* a1p = Ax + 320 * 33;
                float yr0[4] = {0,0,0,0}, yi0[4] = {0,0,0,0};
                float yr1[4] = {0,0,0,0}, yi1[4] = {0,0,0,0};
                #pragma unroll 1
                for (int i = 0; i < 128; i += 4) {
                    float4 wr4[4], wi4[4];
                    float  x0[4], x1[4];
                    #pragma unroll
                    for (int v = 0; v < 4; v++) {
                        wr4[v] = *reinterpret_cast<const float4*>(wp + (i + v) * 256);
                        wi4[v] = *reinterpret_cast<const float4*>(wp + (i + v) * 256 + 128);
                    }
                    #pragma unroll
                    for (int v = 0; v < 4; v++) {
                        x0[v] = a0p[(i + v) * 33];
                        x1[v] = a1p[(i + v) * 33];
                    }
                    #pragma unroll
                    for (int v = 0; v < 4; v++) {
                        float wr[4] = {wr4[v].x, wr4[v].y, wr4[v].z, wr4[v].w};
                        float wi[4] = {wi4[v].x, wi4[v].y, wi4[v].z, wi4[v].w};
                        #pragma unroll
                        for (int u = 0; u < 4; u++) {
                            yr0[u] = fmaf(wr[u], x0[v], yr0[u]);
                            yr1[u] = fmaf(wr[u], x1[v], yr1[u]);
                            yi0[u] = fmaf(wi[u], x0[v], yi0[u]);
                            yi1[u] = fmaf(wi[u], x1[v], yi1[u]);
                        }
                    }
                }
                #pragma unroll
                for (int u = 0; u < 4; u++) {
                    int k = k0 + u;
                    float om = yr0[u] - yi1[u];
                    float op = yr1[u] + yi0[u];
                    int dm = (k < 64) ? (64 + 3 * k)     : (256 + 5 * (k - 64) + 1);
                    int dp = (k < 64) ? (64 + 3 * k + 2) : (256 + 5 * (k - 64) + 3);
                    Bb[dm * 32 + lane] = om;
                    Bb[dp * 32 + lane] = op;
                }
            } else {
                int k0 = (g - 80) * 4;
                const float* wp  = g_Wt2 + b * 8192 + k0;
                const float* a0p = Ax + 448 * 33;
                const float* a1p = Ax + 512 * 33;
                float yr0[4] = {0,0,0,0}, yi0[4] = {0,0,0,0};
                float yr1[4] = {0,0,0,0}, yi1[4] = {0,0,0,0};
                #pragma unroll 1
                for (int i = 0; i < 64; i += 4) {
                    float4 wr4[4], wi4[4];
                    float  x0[4], x1[4];
                    #pragma unroll
                    for (int v = 0; v < 4; v++) {
                        wr4[v] = *reinterpret_cast<const float4*>(wp + (i + v) * 128);
                        wi4[v] = *reinterpret_cast<const float4*>(wp + (i + v) * 128 + 64);
                    }
                    #pragma unroll
                    for (int v = 0; v < 4; v++) {
                        x0[v] = a0p[(i + v) * 33];
                        x1[v] = a1p[(i + v) * 33];
                    }
                    #pragma unroll
                    for (int v = 0; v < 4; v++) {
                        float wr[4] = {wr4[v].x, wr4[v].y, wr4[v].z, wr4[v].w};
                        float wi[4] = {wi4[v].x, wi4[v].y, wi4[v].z, wi4[v].w};
                        #pragma unroll
                        for (int u = 0; u < 4; u++) {
                            yr0[u] = fmaf(wr[u], x0[v], yr0[u]);
                            yr1[u] = fmaf(wr[u], x1[v], yr1[u]);
                            yi0[u] = fmaf(wi[u], x0[v], yi0[u]);
                            yi1[u] = fmaf(wi[u], x1[v], yi1[u]);
                        }
                    }
                }
                #pragma unroll
                for (int u = 0; u < 4; u++) {
                    int k = k0 + u;
                    float om = yr0[u] - yi1[u];
                    float op = yr1[u] + yi0[u];
                    Bb[(256 + 5 * k) * 32 + lane]     = om;
                    Bb[(256 + 5 * k + 4) * 32 + lane] = op;
                }
            }
        }
    }
    __syncthreads();

    // ---- Phase 3: back-rotation (inverse Wigner), write final into A[dim][s] ----
    {
        float e1[9], e2[25];
        #pragma unroll
        for (int j = 0; j < 9; j++)  e1[j] = D1b[lane * 9 + j];
        #pragma unroll
        for (int j = 0; j < 25; j++) e2[j] = D2b[lane * 25 + j];
        const float* bp = Bb + lane;
        float* Ao = A + lane;
        #pragma unroll
        for (int k = 0; k < 4; k++) {
            int c = w + NWARP * k;
            Ao[c * 33] = bp[c * 32];  // l=0 block of D is identity
            float v0 = bp[(64 + 3 * c) * 32], v1 = bp[(64 + 3 * c + 1) * 32], v2 = bp[(64 + 3 * c + 2) * 32];
            Ao[(64 + 3 * c) * 33]     = fmaf(e1[0], v0, fmaf(e1[1], v1, e1[2] * v2));
            Ao[(64 + 3 * c + 1) * 33] = fmaf(e1[3], v0, fmaf(e1[4], v1, e1[5] * v2));
            Ao[(64 + 3 * c + 2) * 33] = fmaf(e1[6], v0, fmaf(e1[7], v1, e1[8] * v2));
            float u0 = bp[(256 + 5 * c) * 32],     u1 = bp[(256 + 5 * c + 1) * 32];
            float u2 = bp[(256 + 5 * c + 2) * 32], u3 = bp[(256 + 5 * c + 3) * 32];
            float u4 = bp[(256 + 5 * c + 4) * 32];
            #pragma unroll
            for (int i = 0; i < 5; i++)
                Ao[(256 + 5 * c + i) * 33] =
                    fmaf(e2[i*5+0], u0, fmaf(e2[i*5+1], u1, fmaf(e2[i*5+2], u2,
                    fmaf(e2[i*5+3], u3, e2[i*5+4] * u4))));
        }
    }
    __syncthreads();

    // ---- Store: coalesced global write ----
    {
        float* og = out + (size_t)n0 * 576;
        for (int idx = tid; idx < TILE * 576; idx += NTHR) {
            int s = idx / 576, d = idx % 576;
            og[idx] = A[d * 33 + s];
        }
    }
}

extern "C" void kernel_launch(void* const* d_in, const int* in_sizes, int n_in,
                              void* d_out, int out_size)
{
    const float* x     = (const float*)d_in[0];
    const float* alpha = (const float*)d_in[1];
    const float* beta  = (const float*)d_in[2];
    const float* gamma_= (const float*)d_in[3];
    const float* coef  = (const float*)d_in[4];
    const float* Jd1   = (const float*)d_in[5];
    const float* Jd2   = (const float*)d_in[6];
    const float* w0    = (const float*)d_in[7];
    const float* b0    = (const float*)d_in[8];
    const float* ws0   = (const float*)d_in[9];
    const float* bs0   = (const float*)d_in[10];
    const float* w1    = (const float*)d_in[11];
    const float* ws1   = (const float*)d_in[12];
    const float* w2    = (const float*)d_in[13];
    const float* ws2   = (const float*)d_in[14];
    float* out = (float*)d_out;

    const int totalW = 8 * 192 * 192 + 8 * 192 + 8 * 128 * 256 + 8 * 64 * 128;
    prep_weights_kernel<<<(totalW + 255) / 256, 256>>>(coef, w0, b0, ws0, bs0,
                                                       w1, ws1, w2, ws2);

    const int smem_bytes = SM_TOT * sizeof(float);
    cudaFuncSetAttribute(so2_main_kernel,
                         cudaFuncAttributeMaxDynamicSharedMemorySize, smem_bytes);
    so2_main_kernel<<<NSAMP / TILE, NTHR, smem_bytes>>>(x, alpha, beta, gamma_,
                                                        Jd1, Jd2, out);
}

// round 4
// speedup vs baseline: 2.5331x; 1.5365x over previous
#include <cuda_runtime.h>
#include <math.h>

#define NSAMP 64000
#define TILE  64
#define NTHR  512
#define SPB   8000

// Precombined (expert-mixed) weights, TRANSPOSED to [b][i][o].
__device__ __align__(16) float g_Wt0[8 * 192 * 192];
__device__ __align__(16) float g_bc0[8 * 192];
__device__ __align__(16) float g_Wt1[8 * 128 * 256];
__device__ __align__(16) float g_Wt2[8 * 64 * 128];
// Pre-back-rotation output, [dim][n] layout for coalesced access both ways.
__device__ float g_tmp[576 * NSAMP];

__global__ void prep_weights_kernel(
    const float* __restrict__ coef,
    const float* __restrict__ w0, const float* __restrict__ b0,
    const float* __restrict__ ws0, const float* __restrict__ bs0,
    const float* __restrict__ w1, const float* __restrict__ ws1,
    const float* __restrict__ w2, const float* __restrict__ ws2)
{
    int idx = blockIdx.x * blockDim.x + threadIdx.x;
    const int S0 = 8 * 192 * 192;
    const int S1 = 8 * 192;
    const int S2 = 8 * 128 * 256;
    const int S3 = 8 * 64 * 128;
    if (idx < S0) {
        int b = idx / 36864, r = idx % 36864;
        int i = r / 192, o = r % 192;
        float v = ws0[o * 192 + i];
        #pragma unroll
        for (int e = 0; e < 8; e++)
            v = fmaf(coef[b * 8 + e], w0[e * 36864 + o * 192 + i], v);
        g_Wt0[b * 36864 + i * 192 + o] = v;
        return;
    }
    idx -= S0;
    if (idx < S1) {
        int b = idx / 192, o = idx % 192;
        float v = bs0[o];
        #pragma unroll
        for (int e = 0; e < 8; e++)
            v = fmaf(coef[b * 8 + e], b0[e * 192 + o], v);
        g_bc0[b * 192 + o] = v;
        return;
    }
    idx -= S1;
    if (idx < S2) {
        int b = idx / 32768, r = idx % 32768;
        int i = r / 256, o = r % 256;
        float v = ws1[o * 128 + i];
        #pragma unroll
        for (int e = 0; e < 8; e++)
            v = fmaf(coef[b * 8 + e], w1[e * 32768 + o * 128 + i], v);
        g_Wt1[b * 32768 + i * 256 + o] = v;
        return;
    }
    idx -= S2;
    if (idx < S3) {
        int b = idx / 8192, r = idx % 8192;
        int i = r / 128, o = r % 128;
        float v = ws2[o * 64 + i];
        #pragma unroll
        for (int e = 0; e < 8; e++)
            v = fmaf(coef[b * 8 + e], w2[e * 8192 + o * 64 + i], v);
        g_Wt2[b * 8192 + i * 128 + o] = v;
    }
}

__device__ __forceinline__ void mm3(const float* P, const float* Q, float* R) {
    #pragma unroll
    for (int i = 0; i < 3; i++)
        #pragma unroll
        for (int j = 0; j < 3; j++) {
            float acc = 0.f;
            #pragma unroll
            for (int k = 0; k < 3; k++) acc = fmaf(P[i * 3 + k], Q[k * 3 + j], acc);
            R[i * 3 + j] = acc;
        }
}
__device__ __forceinline__ void mm5(const float* P, const float* Q, float* R) {
    #pragma unroll
    for (int i = 0; i < 5; i++)
        #pragma unroll
        for (int j = 0; j < 5; j++) {
            float acc = 0.f;
            #pragma unroll
            for (int k = 0; k < 5; k++) acc = fmaf(P[i * 5 + k], Q[k * 5 + j], acc);
            R[i * 5 + j] = acc;
        }
}

__device__ void build_D(float a1, float a2, float a3,
                        const float* __restrict__ J1g,
                        const float* __restrict__ J2g,
                        float* __restrict__ D1, float* __restrict__ D2)
{
    float J1[9], J2[25];
    #pragma unroll
    for (int i = 0; i < 9; i++) J1[i] = J1g[i];
    #pragma unroll
    for (int i = 0; i < 25; i++) J2[i] = J2g[i];

    float X[3][9], Y[3][25];
    float aa[3] = {a1, a2, a3};
    #pragma unroll
    for (int t = 0; t < 3; t++) {
        float c1, s1, c2, s2;
        sincosf(aa[t], &s1, &c1);
        sincosf(2.0f * aa[t], &s2, &c2);
        float* Xp = X[t];
        Xp[0] = c1;  Xp[1] = 0.f; Xp[2] = s1;
        Xp[3] = 0.f; Xp[4] = 1.f; Xp[5] = 0.f;
        Xp[6] = -s1; Xp[7] = 0.f; Xp[8] = c1;
        float* Yp = Y[t];
        #pragma unroll
        for (int q = 0; q < 25; q++) Yp[q] = 0.f;
        Yp[0]  = c2;  Yp[4]  = s2;
        Yp[6]  = c1;  Yp[8]  = s1;
        Yp[12] = 1.f;
        Yp[16] = -s1; Yp[18] = c1;
        Yp[20] = -s2; Yp[24] = c2;
    }
    float T1[9], T2[9];
    mm3(X[0], J1, T1);
    mm3(T1, X[1], T2);
    mm3(T2, J1, T1);
    mm3(T1, X[2], D1);
    float U1[25], U2[25];
    mm5(Y[0], J2, U1);
    mm5(U1, Y[1], U2);
    mm5(U2, J2, U1);
    mm5(U1, Y[2], D2);
}

// Kernel 1 SMEM (floats):
//   A   [576*64]  gathered inputs, col = (s&31)*2 + (s>>5) (halves adjacent)
//   ST  [16*577]  raw-x staging (16 samples per pass)
//   D1f [64*9], D2f [64*25]
#define SM_A    0
#define SM_ST   (576 * 64)
#define SM_D1F  (SM_ST + 16 * 577)
#define SM_D2F  (SM_D1F + 64 * 9)
#define SM1_TOT (SM_D2F + 64 * 25)

__global__ __launch_bounds__(NTHR, 1)
void so2_gemm_kernel(const float* __restrict__ x,
                     const float* __restrict__ alpha,
                     const float* __restrict__ beta,
                     const float* __restrict__ gamma_,
                     const float* __restrict__ Jd1,
                     const float* __restrict__ Jd2)
{
    extern __shared__ float sm[];
    float* A   = sm + SM_A;
    float* ST  = sm + SM_ST;
    float* D1f = sm + SM_D1F;
    float* D2f = sm + SM_D2F;

    const int tid  = threadIdx.x;
    const int w    = tid >> 5;
    const int lane = tid & 31;
    const int n0   = blockIdx.x * TILE;
    const int b    = n0 / SPB;
    const float* xg = x + (size_t)n0 * 576;

    // ---- Phase 1: fwd Wigner build (threads 0-63) + stage pass 0 (64-511) ----
    if (tid < 64) {
        int n = n0 + tid;
        build_D(alpha[n], beta[n], gamma_[n], Jd1, Jd2,
                D1f + tid * 9, D2f + tid * 25);
    } else {
        for (int idx = tid - 64; idx < 16 * 576; idx += NTHR - 64) {
            int s = idx / 576, d = idx % 576;
            ST[s * 577 + d] = xg[idx];
        }
    }
    __syncthreads();

    // ---- 4 passes: gather+rotate 16 samples, then stage next 16 ----
    for (int p = 0; p < 4; p++) {
        {
            int s16 = tid & 15;
            int grp = tid >> 4;
            int s   = p * 16 + s16;
            int s2  = ((s & 31) << 1) | (s >> 5);
            const float* br = ST + s16 * 577;
            float d1[9], d2[25];
            #pragma unroll
            for (int j = 0; j < 9; j++)  d1[j] = D1f[s * 9 + j];
            #pragma unroll
            for (int j = 0; j < 25; j++) d2[j] = D2f[s * 25 + j];
            #pragma unroll
            for (int cc = 0; cc < 2; cc++) {
                int c = grp + 32 * cc;
                A[c * 64 + s2] = br[c];
                float v0 = br[64 + 3 * c], v1 = br[64 + 3 * c + 1], v2 = br[64 + 3 * c + 2];
                A[(192 + c) * 64 + s2] = fmaf(d1[0], v0, fmaf(d1[1], v1, d1[2] * v2));
                A[(64  + c) * 64 + s2] = fmaf(d1[3], v0, fmaf(d1[4], v1, d1[5] * v2));
                A[(320 + c) * 64 + s2] = fmaf(d1[6], v0, fmaf(d1[7], v1, d1[8] * v2));
                float u0 = br[256 + 5 * c],     u1 = br[256 + 5 * c + 1], u2 = br[256 + 5 * c + 2];
                float u3 = br[256 + 5 * c + 3], u4 = br[256 + 5 * c + 4];
                float rr[5];
                #pragma unroll
                for (int i = 0; i < 5; i++)
                    rr[i] = fmaf(d2[i*5+0], u0, fmaf(d2[i*5+1], u1, fmaf(d2[i*5+2], u2,
                            fmaf(d2[i*5+3], u3, d2[i*5+4] * u4))));
                A[(448 + c) * 64 + s2] = rr[0];
                A[(256 + c) * 64 + s2] = rr[1];
                A[(128 + c) * 64 + s2] = rr[2];
                A[(384 + c) * 64 + s2] = rr[3];
                A[(512 + c) * 64 + s2] = rr[4];
            }
        }
        __syncthreads();
        if (p < 3) {
            const float* xp = xg + (p + 1) * 16 * 576;
            for (int idx = tid; idx < 16 * 576; idx += NTHR) {
                int s = idx / 576, d = idx % 576;
                ST[s * 577 + d] = xp[idx];
            }
            __syncthreads();
        }
    }

    // ---- Phase 2: each warp does 3 m0 + 2 m1 + 1 m2 groups ----
    // m0 groups: g = w, w+16, w+32 (o0 = 4g)
    #pragma unroll 1
    for (int t = 0; t < 3; t++) {
        int o0 = (w + 16 * t) * 4;
        const float* wp = g_Wt0 + b * 36864 + o0;
        const float* bp = g_bc0 + b * 192 + o0;
        float aa[4], ab[4];
        #pragma unroll
        for (int u = 0; u < 4; u++) { aa[u] = bp[u]; ab[u] = bp[u]; }
        #pragma unroll 1
        for (int i = 0; i < 192; i += 8) {
            float4 wv[8];
            float2 xv[8];
            #pragma unroll
            for (int u = 0; u < 8; u++)
                wv[u] = *reinterpret_cast<const float4*>(wp + (i + u) * 192);
            #pragma unroll
            for (int u = 0; u < 8; u++)
                xv[u] = *reinterpret_cast<const float2*>(A + (i + u) * 64 + 2 * lane);
            #pragma unroll
            for (int u = 0; u < 8; u++) {
                aa[0] = fmaf(wv[u].x, xv[u].x, aa[0]);
                ab[0] = fmaf(wv[u].x, xv[u].y, ab[0]);
                aa[1] = fmaf(wv[u].y, xv[u].x, aa[1]);
                ab[1] = fmaf(wv[u].y, xv[u].y, ab[1]);
                aa[2] = fmaf(wv[u].z, xv[u].x, aa[2]);
                ab[2] = fmaf(wv[u].z, xv[u].y, ab[2]);
                aa[3] = fmaf(wv[u].w, xv[u].x, aa[3]);
                ab[3] = fmaf(wv[u].w, xv[u].y, ab[3]);
            }
        }
        #pragma unroll
        for (int u = 0; u < 4; u++) {
            int o = o0 + u;
            int dim = (o < 64) ? o : (o < 128) ? (64 + 3 * (o - 64) + 1)
                                               : (256 + 5 * (o - 128) + 2);
            g_tmp[dim * NSAMP + n0 + lane]      = aa[u];
            g_tmp[dim * NSAMP + n0 + 32 + lane] = ab[u];
        }
    }

    // m1 groups: k0 = 4w and 4w+64
    #pragma unroll 1
    for (int t = 0; t < 2; t++) {
        int k0 = 4 * w + 64 * t;
        const float* wp = g_Wt1 + b * 32768 + k0;
        float yr0a[4] = {0,0,0,0}, yr0b[4] = {0,0,0,0};
        float yr1a[4] = {0,0,0,0}, yr1b[4] = {0,0,0,0};
        float yi0a[4] = {0,0,0,0}, yi0b[4] = {0,0,0,0};
        float yi1a[4] = {0,0,0,0}, yi1b[4] = {0,0,0,0};
        #pragma unroll 1
        for (int i = 0; i < 128; i += 2) {
            float4 wr[2], wi[2];
            float2 x0[2], x1[2];
            #pragma unroll
            for (int v = 0; v < 2; v++) {
                wr[v] = *reinterpret_cast<const float4*>(wp + (i + v) * 256);
                wi[v] = *reinterpret_cast<const float4*>(wp + (i + v) * 256 + 128);
                x0[v] = *reinterpret_cast<const float2*>(A + (192 + i + v) * 64 + 2 * lane);
                x1[v] = *reinterpret_cast<const float2*>(A + (320 + i + v) * 64 + 2 * lane);
            }
            #pragma unroll
            for (int v = 0; v < 2; v++) {
                float wrr[4] = {wr[v].x, wr[v].y, wr[v].z, wr[v].w};
                float wii[4] = {wi[v].x, wi[v].y, wi[v].z, wi[v].w};
                #pragma unroll
                for (int u = 0; u < 4; u++) {
                    yr0a[u] = fmaf(wrr[u], x0[v].x, yr0a[u]);
                    yr0b[u] = fmaf(wrr[u], x0[v].y, yr0b[u]);
                    yr1a[u] = fmaf(wrr[u], x1[v].x, yr1a[u]);
                    yr1b[u] = fmaf(wrr[u], x1[v].y, yr1b[u]);
                    yi0a[u] = fmaf(wii[u], x0[v].x, yi0a[u]);
                    yi0b[u] = fmaf(wii[u], x0[v].y, yi0b[u]);
                    yi1a[u] = fmaf(wii[u], x1[v].x, yi1a[u]);
                    yi1b[u] = fmaf(wii[u], x1[v].y, yi1b[u]);
                }
            }
        }
        #pragma unroll
        for (int u = 0; u < 4; u++) {
            int k = k0 + u;
            int dm = (k < 64) ? (64 + 3 * k)     : (256 + 5 * (k - 64) + 1);
            int dp = (k < 64) ? (64 + 3 * k + 2) : (256 + 5 * (k - 64) + 3);
            g_tmp[dm * NSAMP + n0 + lane]      = yr0a[u] - yi1a[u];
            g_tmp[dm * NSAMP + n0 + 32 + lane] = yr0b[u] - yi1b[u];
            g_tmp[dp * NSAMP + n0 + lane]      = yr1a[u] + yi0a[u];
            g_tmp[dp * NSAMP + n0 + 32 + lane] = yr1b[u] + yi0b[u];
        }
    }

    // m2 group: k0 = 4w
    {
        int k0 = 4 * w;
        const float* wp = g_Wt2 + b * 8192 + k0;
        float yr0a[4] = {0,0,0,0}, yr0b[4] = {0,0,0,0};
        float yr1a[4] = {0,0,0,0}, yr1b[4] = {0,0,0,0};
        float yi0a[4] = {0,0,0,0}, yi0b[4] = {0,0,0,0};
        float yi1a[4] = {0,0,0,0}, yi1b[4] = {0,0,0,0};
        #pragma unroll 1
        for (int i = 0; i < 64; i += 2) {
            float4 wr[2], wi[2];
            float2 x0[2], x1[2];
            #pragma unroll
            for (int v = 0; v < 2; v++) {
                wr[v] = *reinterpret_cast<const float4*>(wp + (i + v) * 128);
                wi[v] = *reinterpret_cast<const float4*>(wp + (i + v) * 128 + 64);
                x0[v] = *reinterpret_cast<const float2*>(A + (448 + i + v) * 64 + 2 * lane);
                x1[v] = *reinterpret_cast<const float2*>(A + (512 + i + v) * 64 + 2 * lane);
            }
            #pragma unroll
            for (int v = 0; v < 2; v++) {
                float wrr[4] = {wr[v].x, wr[v].y, wr[v].z, wr[v].w};
                float wii[4] = {wi[v].x, wi[v].y, wi[v].z, wi[v].w};
                #pragma unroll
                for (int u = 0; u < 4; u++) {
                    yr0a[u] = fmaf(wrr[u], x0[v].x, yr0a[u]);
                    yr0b[u] = fmaf(wrr[u], x0[v].y, yr0b[u]);
                    yr1a[u] = fmaf(wrr[u], x1[v].x, yr1a[u]);
                    yr1b[u] = fmaf(wrr[u], x1[v].y, yr1b[u]);
                    yi0a[u] = fmaf(wii[u], x0[v].x, yi0a[u]);
                    yi0b[u] = fmaf(wii[u], x0[v].y, yi0b[u]);
                    yi1a[u] = fmaf(wii[u], x1[v].x, yi1a[u]);
                    yi1b[u] = fmaf(wii[u], x1[v].y, yi1b[u]);
                }
            }
        }
        #pragma unroll
        for (int u = 0; u < 4; u++) {
            int k = k0 + u;
            g_tmp[(256 + 5 * k) * NSAMP + n0 + lane]          = yr0a[u] - yi1a[u];
            g_tmp[(256 + 5 * k) * NSAMP + n0 + 32 + lane]     = yr0b[u] - yi1b[u];
            g_tmp[(256 + 5 * k + 4) * NSAMP + n0 + lane]      = yr1a[u] + yi0a[u];
            g_tmp[(256 + 5 * k + 4) * NSAMP + n0 + 32 + lane] = yr1b[u] + yi0b[u];
        }
    }
}

// Kernel 2: back-rotation. 32 samples/block, in-smem, coalesced both ways.
#define K2THR 256
#define SM2_S   0
#define SM2_D1B (576 * 33)
#define SM2_D2B (SM2_D1B + 32 * 9)
#define SM2_TOT (SM2_D2B + 32 * 25)

__global__ __launch_bounds__(K2THR, 1)
void so2_backrot_kernel(const float* __restrict__ alpha,
                        const float* __restrict__ beta,
                        const float* __restrict__ gamma_,
                        const float* __restrict__ Jd1,
                        const float* __restrict__ Jd2,
                        float* __restrict__ out)
{
    extern __shared__ float sm[];
    float* S   = sm + SM2_S;
    float* D1b = sm + SM2_D1B;
    float* D2b = sm + SM2_D2B;

    const int tid  = threadIdx.x;
    const int w    = tid >> 5;
    const int lane = tid & 31;
    const int n0   = blockIdx.x * 32;

    // Load pre-rotation outputs (coalesced over samples)
    for (int idx = tid; idx < 576 * 32; idx += K2THR) {
        int d = idx >> 5, s = idx & 31;
        S[d * 33 + s] = g_tmp[d * NSAMP + n0 + s];
    }
    if (tid < 32) {
        int n = n0 + tid;
        build_D(-gamma_[n], -beta[n], -alpha[n], Jd1, Jd2,
                D1b + tid * 9, D2b + tid * 25);
    }
    __syncthreads();

    // In-place rotation: 8 warps x 8 channels, lane = sample
    {
        float e1[9], e2[25];
        #pragma unroll
        for (int j = 0; j < 9; j++)  e1[j] = D1b[lane * 9 + j];
        #pragma unroll
        for (int j = 0; j < 25; j++) e2[j] = D2b[lane * 25 + j];
        #pragma unroll
        for (int k = 0; k < 8; k++) {
            int c = w + 8 * k;
            float v0 = S[(64 + 3 * c) * 33 + lane];
            float v1 = S[(64 + 3 * c + 1) * 33 + lane];
            float v2 = S[(64 + 3 * c + 2) * 33 + lane];
            S[(64 + 3 * c) * 33 + lane]     = fmaf(e1[0], v0, fmaf(e1[1], v1, e1[2] * v2));
            S[(64 + 3 * c + 1) * 33 + lane] = fmaf(e1[3], v0, fmaf(e1[4], v1, e1[5] * v2));
            S[(64 + 3 * c + 2) * 33 + lane] = fmaf(e1[6], v0, fmaf(e1[7], v1, e1[8] * v2));
            float u0 = S[(256 + 5 * c) * 33 + lane];
            float u1 = S[(256 + 5 * c + 1) * 33 + lane];
            float u2 = S[(256 + 5 * c + 2) * 33 + lane];
            float u3 = S[(256 + 5 * c + 3) * 33 + lane];
            float u4 = S[(256 + 5 * c + 4) * 33 + lane];
            #pragma unroll
            for (int i = 0; i < 5; i++)
                S[(256 + 5 * c + i) * 33 + lane] =
                    fmaf(e2[i*5+0], u0, fmaf(e2[i*5+1], u1, fmaf(e2[i*5+2], u2,
                    fmaf(e2[i*5+3], u3, e2[i*5+4] * u4))));
        }
    }
    __syncthreads();

    // Coalesced final store
    for (int idx = tid; idx < 32 * 576; idx += K2THR) {
        int s = idx / 576, d = idx % 576;
        out[(size_t)(n0 + s) * 576 + d] = S[d * 33 + s];
    }
}

extern "C" void kernel_launch(void* const* d_in, const int* in_sizes, int n_in,
                              void* d_out, int out_size)
{
    const float* x     = (const float*)d_in[0];
    const float* alpha = (const float*)d_in[1];
    const float* beta  = (const float*)d_in[2];
    const float* gamma_= (const float*)d_in[3];
    const float* coef  = (const float*)d_in[4];
    const float* Jd1   = (const float*)d_in[5];
    const float* Jd2   = (const float*)d_in[6];
    const float* w0    = (const float*)d_in[7];
    const float* b0    = (const float*)d_in[8];
    const float* ws0   = (const float*)d_in[9];
    const float* bs0   = (const float*)d_in[10];
    const float* w1    = (const float*)d_in[11];
    const float* ws1   = (const float*)d_in[12];
    const float* w2    = (const float*)d_in[13];
    const float* ws2   = (const float*)d_in[14];
    float* out = (float*)d_out;

    const int totalW = 8 * 192 * 192 + 8 * 192 + 8 * 128 * 256 + 8 * 64 * 128;
    prep_weights_kernel<<<(totalW + 255) / 256, 256>>>(coef, w0, b0, ws0, bs0,
                                                       w1, ws1, w2, ws2);

    const int smem1 = SM1_TOT * sizeof(float);
    cudaFuncSetAttribute(so2_gemm_kernel,
                         cudaFuncAttributeMaxDynamicSharedMemorySize, smem1);
    so2_gemm_kernel<<<NSAMP / TILE, NTHR, smem1>>>(x, alpha, beta, gamma_, Jd1, Jd2);

    const int smem2 = SM2_TOT * sizeof(float);
    cudaFuncSetAttribute(so2_backrot_kernel,
                         cudaFuncAttributeMaxDynamicSharedMemorySize, smem2);
    so2_backrot_kernel<<<NSAMP / 32, K2THR, smem2>>>(alpha, beta, gamma_,
                                                     Jd1, Jd2, out);
}